// round 1
// baseline (speedup 1.0000x reference)
#include <cuda_runtime.h>
#include <cuda_bf16.h>

// CovarianceResidualError:
//   a_i        = graph_emb[i, 0]
//   ACC_j      = sum_i errors[i,j] * a_i
//   SE_j       = sum_i errors[i,j]
//   SA         = sum_i a_i
//   col_sums_j = ACC_j - SA*SE_j/N        (mean-centering identity)
//   out        = -sum_j |col_sums_j|
//
// Kernel 1: 512 blocks x 256 threads, deterministic per-block partials.
// Kernel 2: 1 block x 512 threads, deterministic final reduction.

#define NROWS 131072
#define OCOLS 256
#define DCOLS 128
#define NB 512
#define ROWS_PER_BLK (NROWS / NB)          // 256
#define CHUNK 64
#define NCHUNK (ROWS_PER_BLK / CHUNK)      // 4

__device__ float g_pacc[NB * OCOLS];
__device__ float g_pse [NB * OCOLS];
__device__ float g_psa [NB];

__global__ void __launch_bounds__(256, 4)
cov_partial_kernel(const float* __restrict__ ge, const float4* __restrict__ err4)
{
    __shared__ float a_sh[CHUNK];
    __shared__ float red[4 * OCOLS];

    const int tid  = threadIdx.x;
    const int tx   = tid & 63;     // column group: columns 4*tx .. 4*tx+3
    const int ty   = tid >> 6;     // row phase 0..3
    const int row0 = blockIdx.x * ROWS_PER_BLK;

    float4 acc = make_float4(0.f, 0.f, 0.f, 0.f);
    float4 se  = make_float4(0.f, 0.f, 0.f, 0.f);
    float  suma = 0.f;

    // Prefetch a-column chunk 0 (strided loads: one per row)
    float a_next = 0.f;
    if (tid < CHUNK)
        a_next = ge[(size_t)(row0 + tid) * DCOLS];

    for (int c = 0; c < NCHUNK; ++c) {
        const int base = row0 + c * CHUNK;
        __syncthreads();                       // a_sh from previous chunk fully consumed
        if (tid < CHUNK) { a_sh[tid] = a_next; suma += a_next; }
        __syncthreads();
        if (tid < CHUNK && (c + 1) < NCHUNK)   // prefetch next chunk's a-column
            a_next = ge[(size_t)(base + CHUNK + tid) * DCOLS];

        #pragma unroll
        for (int r = ty; r < CHUNK; r += 4) {
            const float4 e = err4[(size_t)(base + r) * (OCOLS / 4) + tx];
            const float  a = a_sh[r];
            acc.x += e.x * a; acc.y += e.y * a;
            acc.z += e.z * a; acc.w += e.w * a;
            se.x  += e.x;     se.y  += e.y;
            se.z  += e.z;     se.w  += e.w;
        }
    }

    // Reduce across the 4 row phases (deterministic, via shared)
    __syncthreads();
    red[ty * OCOLS + 4 * tx + 0] = acc.x;
    red[ty * OCOLS + 4 * tx + 1] = acc.y;
    red[ty * OCOLS + 4 * tx + 2] = acc.z;
    red[ty * OCOLS + 4 * tx + 3] = acc.w;
    __syncthreads();
    {
        const float tot = red[tid] + red[OCOLS + tid] + red[2 * OCOLS + tid] + red[3 * OCOLS + tid];
        g_pacc[blockIdx.x * OCOLS + tid] = tot;
    }
    __syncthreads();
    red[ty * OCOLS + 4 * tx + 0] = se.x;
    red[ty * OCOLS + 4 * tx + 1] = se.y;
    red[ty * OCOLS + 4 * tx + 2] = se.z;
    red[ty * OCOLS + 4 * tx + 3] = se.w;
    __syncthreads();
    {
        const float tot = red[tid] + red[OCOLS + tid] + red[2 * OCOLS + tid] + red[3 * OCOLS + tid];
        g_pse[blockIdx.x * OCOLS + tid] = tot;
    }

    // Block partial of SA (deterministic fixed-order sum over 64 values)
    __syncthreads();
    if (tid < CHUNK) red[tid] = suma;
    __syncthreads();
    if (tid == 0) {
        float s = 0.f;
        #pragma unroll
        for (int i = 0; i < CHUNK; ++i) s += red[i];
        g_psa[blockIdx.x] = s;
    }
}

__global__ void __launch_bounds__(512, 1)
cov_final_kernel(float* __restrict__ out)
{
    __shared__ float4 shacc[8][64];
    __shared__ float4 shse [8][64];
    __shared__ float  shr[512];

    const int tid = threadIdx.x;

    // ---- SA = sum of block partials (fixed-order tree reduce) ----
    float sa = 0.f;
    for (int b = tid; b < NB; b += 512) sa += g_psa[b];
    shr[tid] = sa;
    __syncthreads();
    #pragma unroll
    for (int s = 256; s > 0; s >>= 1) {
        if (tid < s) shr[tid] += shr[tid + s];
        __syncthreads();
    }
    const float S_a = shr[0];
    __syncthreads();

    // ---- reduce per-column partials over the 512 blocks (coalesced float4) ----
    const int cg = tid & 63;   // column group
    const int bg = tid >> 6;   // 0..7
    const float4* pacc4 = (const float4*)g_pacc;
    const float4* pse4  = (const float4*)g_pse;
    float4 av = make_float4(0.f, 0.f, 0.f, 0.f);
    float4 sv = make_float4(0.f, 0.f, 0.f, 0.f);
    for (int b = bg; b < NB; b += 8) {
        const float4 x = pacc4[b * 64 + cg];
        const float4 y = pse4 [b * 64 + cg];
        av.x += x.x; av.y += x.y; av.z += x.z; av.w += x.w;
        sv.x += y.x; sv.y += y.y; sv.z += y.z; sv.w += y.w;
    }
    shacc[bg][cg] = av;
    shse [bg][cg] = sv;
    __syncthreads();

    float v = 0.f;
    if (tid < 64) {
        float4 A = make_float4(0.f, 0.f, 0.f, 0.f);
        float4 S = make_float4(0.f, 0.f, 0.f, 0.f);
        #pragma unroll
        for (int g = 0; g < 8; ++g) {
            const float4 x = shacc[g][tid];
            const float4 y = shse [g][tid];
            A.x += x.x; A.y += x.y; A.z += x.z; A.w += x.w;
            S.x += y.x; S.y += y.y; S.z += y.z; S.w += y.w;
        }
        const float k = S_a * (1.0f / (float)NROWS);
        v = fabsf(A.x - k * S.x) + fabsf(A.y - k * S.y)
          + fabsf(A.z - k * S.z) + fabsf(A.w - k * S.w);
    }
    __syncthreads();
    shr[tid] = v;     // threads >= 64 contribute 0
    __syncthreads();
    #pragma unroll
    for (int s = 256; s > 0; s >>= 1) {
        if (tid < s) shr[tid] += shr[tid + s];
        __syncthreads();
    }
    if (tid == 0) out[0] = -shr[0];
}

extern "C" void kernel_launch(void* const* d_in, const int* in_sizes, int n_in,
                              void* d_out, int out_size)
{
    const float* ge  = nullptr;   // graph_emb (N x 128)
    const float* err = nullptr;   // errors    (N x 256)
    for (int i = 0; i < n_in; ++i) {
        if (in_sizes[i] == NROWS * DCOLS) ge  = (const float*)d_in[i];
        else if (in_sizes[i] == NROWS * OCOLS) err = (const float*)d_in[i];
    }

    cov_partial_kernel<<<NB, 256>>>(ge, (const float4*)err);
    cov_final_kernel<<<1, 512>>>((float*)d_out);
}